// round 1
// baseline (speedup 1.0000x reference)
#include <cuda_runtime.h>
#include <cuda_bf16.h>

#define BB 4
#define HH 16
#define SS 4096
#define DD 64
#define NHEAD (BB*HH)
#define CHUNK 512
#define NCHUNK (SS/CHUNK)
#define TILE 32
#define EPSF 1e-6f

// scratch: per-head kv_term [64][64] and k_one [64]
__device__ float g_kv[NHEAD*DD*DD];
__device__ float g_k1[NHEAD*DD];

__device__ __forceinline__ float phi_f(float x){
    // elu(x)+1 : x>0 -> x+1 ; x<=0 -> exp(x)
    return x > 0.0f ? x + 1.0f : __expf(x);
}

__global__ void zero_kernel(){
    int i = blockIdx.x*blockDim.x + threadIdx.x;
    if (i < NHEAD*DD*DD) g_kv[i] = 0.0f;
    if (i < NHEAD*DD)    g_k1[i] = 0.0f;
}

// kv_term accumulation: grid (NHEAD, NCHUNK), 256 threads.
// thread (ty,tx) owns d-rows [4ty,4ty+4) x v-cols [4tx,4tx+4).
__global__ __launch_bounds__(256) void kv_kernel(const float* __restrict__ K,
                                                 const float* __restrict__ V,
                                                 const float* __restrict__ mask){
    int head = blockIdx.x;
    int b = head / HH;
    int tid = threadIdx.x;
    int tx = tid & 15;
    int ty = tid >> 4;
    __shared__ float sK[TILE][DD];
    __shared__ float sV[TILE][DD];
    float acc[4][4];
    #pragma unroll
    for (int i=0;i<4;i++)
        #pragma unroll
        for (int j=0;j<4;j++) acc[i][j] = 0.0f;
    float k1[4] = {0.f,0.f,0.f,0.f};

    const float* Kb = K + (size_t)head*SS*DD;
    const float* Vb = V + (size_t)head*SS*DD;
    const float* Mb = mask + (size_t)b*SS;
    int s0 = blockIdx.y * CHUNK;

    for (int t = 0; t < CHUNK; t += TILE){
        // cooperative load of TILE rows of K (phi+mask applied) and V
        for (int i = tid; i < TILE*DD/4; i += 256){
            int r = i >> 4;        // row in tile (D/4 = 16 float4 per row)
            int c = i & 15;
            int row = s0 + t + r;
            float4 kk = ((const float4*)(Kb + (size_t)row*DD))[c];
            float m = Mb[row];
            kk.x = phi_f(kk.x)*m; kk.y = phi_f(kk.y)*m;
            kk.z = phi_f(kk.z)*m; kk.w = phi_f(kk.w)*m;
            ((float4*)&sK[r][0])[c] = kk;
            ((float4*)&sV[r][0])[c] = ((const float4*)(Vb + (size_t)row*DD))[c];
        }
        __syncthreads();
        #pragma unroll 4
        for (int r = 0; r < TILE; r++){
            float4 kk = ((const float4*)&sK[r][0])[ty];
            float4 vv = ((const float4*)&sV[r][0])[tx];
            float kx[4] = {kk.x, kk.y, kk.z, kk.w};
            float vx[4] = {vv.x, vv.y, vv.z, vv.w};
            #pragma unroll
            for (int i=0;i<4;i++)
                #pragma unroll
                for (int j=0;j<4;j++)
                    acc[i][j] += kx[i]*vx[j];
            if (tx == 0){
                #pragma unroll
                for (int i=0;i<4;i++) k1[i] += kx[i];
            }
        }
        __syncthreads();
    }

    float* dst = g_kv + (size_t)head*DD*DD;
    #pragma unroll
    for (int i=0;i<4;i++)
        #pragma unroll
        for (int j=0;j<4;j++)
            atomicAdd(&dst[(ty*4+i)*DD + (tx*4+j)], acc[i][j]);
    if (tx == 0){
        #pragma unroll
        for (int i=0;i<4;i++) atomicAdd(&g_k1[head*DD + ty*4+i], k1[i]);
    }
}

// output GEMM + normalizer: grid (NHEAD, SS/128), 128 threads, one row per thread.
__global__ __launch_bounds__(128) void out_kernel(const float* __restrict__ Q,
                                                  float* __restrict__ O){
    int head = blockIdx.x;
    int tid = threadIdx.x;
    __shared__ float skv[DD*DD];
    __shared__ float sk1[DD];
    const float4* src = (const float4*)(g_kv + (size_t)head*DD*DD);
    for (int i = tid; i < DD*DD/4; i += 128) ((float4*)skv)[i] = src[i];
    if (tid < DD) sk1[tid] = g_k1[head*DD + tid];
    __syncthreads();

    int row = blockIdx.y*128 + tid;
    const float* q = Q + ((size_t)head*SS + row)*DD;

    float4 acc[16];
    #pragma unroll
    for (int i=0;i<16;i++) acc[i] = make_float4(0.f,0.f,0.f,0.f);
    float norm = 0.0f;

    #pragma unroll 1
    for (int d4 = 0; d4 < 16; d4++){
        float4 qv = ((const float4*)q)[d4];
        float p[4];
        p[0] = phi_f(qv.x*0.125f);
        p[1] = phi_f(qv.y*0.125f);
        p[2] = phi_f(qv.z*0.125f);
        p[3] = phi_f(qv.w*0.125f);
        #pragma unroll
        for (int k=0;k<4;k++){
            int d = d4*4 + k;
            norm += p[k]*sk1[d];
            const float4* kvrow = (const float4*)(skv + d*DD);
            #pragma unroll
            for (int v4=0; v4<16; v4++){
                float4 kv = kvrow[v4];
                acc[v4].x += p[k]*kv.x;
                acc[v4].y += p[k]*kv.y;
                acc[v4].z += p[k]*kv.z;
                acc[v4].w += p[k]*kv.w;
            }
        }
    }

    float inv = 1.0f / (norm + EPSF);
    float4* out = (float4*)(O + ((size_t)head*SS + row)*DD);
    #pragma unroll
    for (int i=0;i<16;i++){
        float4 a = acc[i];
        a.x *= inv; a.y *= inv; a.z *= inv; a.w *= inv;
        out[i] = a;
    }
}

extern "C" void kernel_launch(void* const* d_in, const int* in_sizes, int n_in,
                              void* d_out, int out_size){
    const float* Q    = (const float*)d_in[0];
    const float* K    = (const float*)d_in[1];
    const float* V    = (const float*)d_in[2];
    const float* mask = (const float*)d_in[3];
    float* O = (float*)d_out;

    zero_kernel<<<(NHEAD*DD*DD + 255)/256, 256>>>();
    kv_kernel<<<dim3(NHEAD, NCHUNK), 256>>>(K, V, mask);
    out_kernel<<<dim3(NHEAD, SS/128), 128>>>(Q, O);
}

// round 2
// speedup vs baseline: 1.0788x; 1.0788x over previous
#include <cuda_runtime.h>
#include <cuda_bf16.h>

#define BB 4
#define HH 16
#define SS 4096
#define DD 64
#define NHEAD (BB*HH)
#define NCHUNK 16
#define CHUNK (SS/NCHUNK)    // 256
#define TILE 32
#define EPSF 1e-6f

typedef unsigned long long u64;

// scratch: per-head kv_term [64][64] and k_one [64]
__device__ float g_kv[NHEAD*DD*DD];
__device__ float g_k1[NHEAD*DD];

__device__ __forceinline__ float phi_f(float x){
    // elu(x)+1 : x>0 -> x+1 ; x<=0 -> exp(x)
    return x > 0.0f ? x + 1.0f : __expf(x);
}

__device__ __forceinline__ u64 pack2(float a, float b){
    u64 r; asm("mov.b64 %0, {%1, %2};" : "=l"(r) : "f"(a), "f"(b)); return r;
}
__device__ __forceinline__ void fma2(u64& d, u64 a, u64 b){
    asm("fma.rn.f32x2 %0, %1, %2, %0;" : "+l"(d) : "l"(a), "l"(b));
}
__device__ __forceinline__ float2 unpack2(u64 v){
    float2 f; asm("mov.b64 {%0, %1}, %2;" : "=f"(f.x), "=f"(f.y) : "l"(v)); return f;
}

__global__ void zero_kernel(){
    int i = blockIdx.x*blockDim.x + threadIdx.x;
    if (i < NHEAD*DD*DD) g_kv[i] = 0.0f;
    if (i < NHEAD*DD)    g_k1[i] = 0.0f;
}

// kv_term accumulation: grid (NHEAD, NCHUNK), 128 threads.
// thread tile: 4 d-rows (ty) x 8 v-cols (tx) of the 64x64 kv matrix.
__global__ __launch_bounds__(128) void kv_kernel(const float* __restrict__ K,
                                                 const float* __restrict__ V,
                                                 const float* __restrict__ mask){
    int head = blockIdx.x;
    int b = head / HH;
    int tid = threadIdx.x;
    int tx = tid & 7;      // v group: cols [tx*8, tx*8+8)
    int ty = tid >> 3;     // d group: rows [ty*4, ty*4+4)

    __shared__ float sK[TILE][DD];
    __shared__ float sV[TILE][DD];

    u64 acc[4][4];
    #pragma unroll
    for (int i=0;i<4;i++)
        #pragma unroll
        for (int j=0;j<4;j++) acc[i][j] = 0ull;
    float4 k1acc = make_float4(0.f,0.f,0.f,0.f);

    const float* Kb = K + (size_t)head*SS*DD;
    const float* Vb = V + (size_t)head*SS*DD;
    const float* Mb = mask + (size_t)b*SS;
    int s0 = blockIdx.y * CHUNK;

    // loader coords: each thread always loads column-group lc (16 float4 groups/row)
    int lc  = tid & 15;
    int lr0 = tid >> 4;    // 0..7, row stride 8

    for (int t = 0; t < CHUNK; t += TILE){
        __syncthreads();
        #pragma unroll
        for (int r = lr0; r < TILE; r += 8){
            int row = s0 + t + r;
            float4 kk = ((const float4*)(Kb + (size_t)row*DD))[lc];
            float m = Mb[row];
            kk.x = phi_f(kk.x)*m; kk.y = phi_f(kk.y)*m;
            kk.z = phi_f(kk.z)*m; kk.w = phi_f(kk.w)*m;
            ((float4*)&sK[r][0])[lc] = kk;
            k1acc.x += kk.x; k1acc.y += kk.y; k1acc.z += kk.z; k1acc.w += kk.w;
            ((float4*)&sV[r][0])[lc] = ((const float4*)(Vb + (size_t)row*DD))[lc];
        }
        __syncthreads();
        #pragma unroll 8
        for (int r = 0; r < TILE; r++){
            float4 kk = ((const float4*)&sK[r][0])[ty];
            u64 kd0 = pack2(kk.x, kk.x);
            u64 kd1 = pack2(kk.y, kk.y);
            u64 kd2 = pack2(kk.z, kk.z);
            u64 kd3 = pack2(kk.w, kk.w);
            const u64* vrow = (const u64*)&sV[r][tx*8];
            u64 v0 = vrow[0], v1 = vrow[1], v2 = vrow[2], v3 = vrow[3];
            fma2(acc[0][0], kd0, v0); fma2(acc[0][1], kd0, v1);
            fma2(acc[0][2], kd0, v2); fma2(acc[0][3], kd0, v3);
            fma2(acc[1][0], kd1, v0); fma2(acc[1][1], kd1, v1);
            fma2(acc[1][2], kd1, v2); fma2(acc[1][3], kd1, v3);
            fma2(acc[2][0], kd2, v0); fma2(acc[2][1], kd2, v1);
            fma2(acc[2][2], kd2, v2); fma2(acc[2][3], kd2, v3);
            fma2(acc[3][0], kd3, v0); fma2(acc[3][1], kd3, v1);
            fma2(acc[3][2], kd3, v2); fma2(acc[3][3], kd3, v3);
        }
    }

    float* dst = g_kv + (size_t)head*DD*DD;
    #pragma unroll
    for (int i=0;i<4;i++){
        int d = ty*4 + i;
        #pragma unroll
        for (int j=0;j<4;j++){
            float2 a = unpack2(acc[i][j]);
            atomicAdd(&dst[d*DD + tx*8 + 2*j    ], a.x);
            atomicAdd(&dst[d*DD + tx*8 + 2*j + 1], a.y);
        }
    }
    atomicAdd(&g_k1[head*DD + lc*4 + 0], k1acc.x);
    atomicAdd(&g_k1[head*DD + lc*4 + 1], k1acc.y);
    atomicAdd(&g_k1[head*DD + lc*4 + 2], k1acc.z);
    atomicAdd(&g_k1[head*DD + lc*4 + 3], k1acc.w);
}

// output GEMM + normalizer: grid (NHEAD, SS/256), 128 threads, 2 rows per thread.
__global__ __launch_bounds__(128) void out_kernel(const float* __restrict__ Q,
                                                  float* __restrict__ O){
    int head = blockIdx.x;
    int tid = threadIdx.x;
    __shared__ float skv[DD*DD];
    __shared__ float sk1[DD];
    const float4* src = (const float4*)(g_kv + (size_t)head*DD*DD);
    #pragma unroll
    for (int i = tid; i < DD*DD/4; i += 128) ((float4*)skv)[i] = src[i];
    if (tid < DD) sk1[tid] = g_k1[head*DD + tid];
    __syncthreads();

    int row0 = blockIdx.y*256 + tid;
    int row1 = row0 + 128;
    const float* q0 = Q + ((size_t)head*SS + row0)*DD;
    const float* q1 = Q + ((size_t)head*SS + row1)*DD;

    u64 acc0[32], acc1[32];
    #pragma unroll
    for (int j=0;j<32;j++){ acc0[j] = 0ull; acc1[j] = 0ull; }
    float n0 = 0.0f, n1 = 0.0f;

    #pragma unroll 1
    for (int d4 = 0; d4 < 16; d4++){
        float4 qa = ((const float4*)q0)[d4];
        float4 qb = ((const float4*)q1)[d4];
        float pa[4], pb[4];
        pa[0] = phi_f(qa.x*0.125f); pa[1] = phi_f(qa.y*0.125f);
        pa[2] = phi_f(qa.z*0.125f); pa[3] = phi_f(qa.w*0.125f);
        pb[0] = phi_f(qb.x*0.125f); pb[1] = phi_f(qb.y*0.125f);
        pb[2] = phi_f(qb.z*0.125f); pb[3] = phi_f(qb.w*0.125f);
        #pragma unroll
        for (int k=0;k<4;k++){
            int d = d4*4 + k;
            u64 ppa = pack2(pa[k], pa[k]);
            u64 ppb = pack2(pb[k], pb[k]);
            n0 += pa[k]*sk1[d];
            n1 += pb[k]*sk1[d];
            const u64* kvrow = (const u64*)(skv + d*DD);
            #pragma unroll
            for (int j=0;j<32;j++){
                u64 kv = kvrow[j];
                fma2(acc0[j], ppa, kv);
                fma2(acc1[j], ppb, kv);
            }
        }
    }

    float i0 = 1.0f / (n0 + EPSF);
    float i1 = 1.0f / (n1 + EPSF);
    float4* out0 = (float4*)(O + ((size_t)head*SS + row0)*DD);
    float4* out1 = (float4*)(O + ((size_t)head*SS + row1)*DD);
    #pragma unroll
    for (int j2=0;j2<16;j2++){
        float2 a = unpack2(acc0[2*j2]);
        float2 b = unpack2(acc0[2*j2+1]);
        out0[j2] = make_float4(a.x*i0, a.y*i0, b.x*i0, b.y*i0);
        float2 c = unpack2(acc1[2*j2]);
        float2 e = unpack2(acc1[2*j2+1]);
        out1[j2] = make_float4(c.x*i1, c.y*i1, e.x*i1, e.y*i1);
    }
}

extern "C" void kernel_launch(void* const* d_in, const int* in_sizes, int n_in,
                              void* d_out, int out_size){
    const float* Q    = (const float*)d_in[0];
    const float* K    = (const float*)d_in[1];
    const float* V    = (const float*)d_in[2];
    const float* mask = (const float*)d_in[3];
    float* O = (float*)d_out;

    zero_kernel<<<(NHEAD*DD*DD + 255)/256, 256>>>();
    kv_kernel<<<dim3(NHEAD, NCHUNK), 128>>>(K, V, mask);
    out_kernel<<<dim3(NHEAD, SS/256), 128>>>(Q, O);
}

// round 3
// speedup vs baseline: 1.7582x; 1.6298x over previous
#include <cuda_runtime.h>
#include <cuda_bf16.h>
#include <cstdint>

#define BB 4
#define HH 16
#define SS 4096
#define DD 64
#define NHEAD (BB*HH)
#define NCHUNK 16
#define CHUNK (SS/NCHUNK)   // 256
#define KT 32               // s-rows per smem tile in kv kernel
#define EPSF 1e-6f
#define KSTRIDE 72          // padded cols: conflict-free for (tig*72 + gid) pattern
#define QSTRIDE 76          // padded cols: conflict-free for (gid*76 + tig) pattern

// scratch: per-head kv_term [64][64] and k_one [64]
__device__ float g_kv[NHEAD*DD*DD];
__device__ float g_k1[NHEAD*DD];

__device__ __forceinline__ float phi_f(float x){
    // elu(x)+1 : x>0 -> x+1 ; x<=0 -> exp(x)
    return x > 0.0f ? x + 1.0f : __expf(x);
}
__device__ __forceinline__ float tf32r(float x){
    float r; asm("cvt.rna.tf32.f32 %0, %1;" : "=f"(r) : "f"(x)); return r;
}
__device__ __forceinline__ void mma_tf32(float c[4],
                                         uint32_t a0, uint32_t a1, uint32_t a2, uint32_t a3,
                                         uint32_t b0, uint32_t b1){
    asm("mma.sync.aligned.m16n8k8.row.col.f32.tf32.tf32.f32 "
        "{%0,%1,%2,%3},{%4,%5,%6,%7},{%8,%9},{%0,%1,%2,%3};"
        : "+f"(c[0]), "+f"(c[1]), "+f"(c[2]), "+f"(c[3])
        : "r"(a0), "r"(a1), "r"(a2), "r"(a3), "r"(b0), "r"(b1));
}

__global__ void zero_kernel(){
    int i = blockIdx.x*blockDim.x + threadIdx.x;
    if (i < NHEAD*DD*DD) g_kv[i] = 0.0f;
    if (i < NHEAD*DD)    g_k1[i] = 0.0f;
}

// KV accumulation via tf32 MMA.
// C[64 d][72] per head-chunk; N-tile 8 (cols 64..71) computes k1 via ones-column in V.
// grid (NHEAD, NCHUNK), 128 threads = 4 warps; warp w owns d-rows [16w,16w+16), all N.
__global__ __launch_bounds__(128) void kv_kernel(const float* __restrict__ K,
                                                 const float* __restrict__ V,
                                                 const float* __restrict__ mask){
    int head = blockIdx.x;
    int b = head / HH;
    int tid  = threadIdx.x;
    int lane = tid & 31, warp = tid >> 5;
    int gid  = lane >> 2, tig = lane & 3;

    __shared__ float sK[KT][KSTRIDE];   // phi(K)*mask, tf32-rounded; [s][d]
    __shared__ float sV[KT][KSTRIDE];   // V tf32-rounded; [s][v]; col64=1, 65..71=0

    // one-time pad init for sV (cols 64..71 never rewritten by loaders)
    for (int i = tid; i < KT*8; i += 128){
        int r = i >> 3, cc = 64 + (i & 7);
        sV[r][cc] = (cc == 64) ? 1.0f : 0.0f;
    }

    float c[9][4];
    #pragma unroll
    for (int nt=0; nt<9; nt++){ c[nt][0]=0.f; c[nt][1]=0.f; c[nt][2]=0.f; c[nt][3]=0.f; }

    const float* Kb = K + (size_t)head*SS*DD;
    const float* Vb = V + (size_t)head*SS*DD;
    const float* Mb = mask + (size_t)b*SS;
    int s0 = blockIdx.y * CHUNK;
    int m_base = warp * 16;

    for (int t = 0; t < CHUNK; t += KT){
        __syncthreads();
        // load KT rows of K (phi+mask) and V; 32 rows x 16 float4 each
        for (int i = tid; i < KT*16; i += 128){
            int r = i >> 4, c4 = i & 15;
            int row = s0 + t + r;
            float4 kk = ((const float4*)(Kb + (size_t)row*DD))[c4];
            float m = Mb[row];
            kk.x = tf32r(phi_f(kk.x)*m); kk.y = tf32r(phi_f(kk.y)*m);
            kk.z = tf32r(phi_f(kk.z)*m); kk.w = tf32r(phi_f(kk.w)*m);
            ((float4*)&sK[r][0])[c4] = kk;
            float4 vv = ((const float4*)(Vb + (size_t)row*DD))[c4];
            vv.x = tf32r(vv.x); vv.y = tf32r(vv.y);
            vv.z = tf32r(vv.z); vv.w = tf32r(vv.w);
            ((float4*)&sV[r][0])[c4] = vv;
        }
        __syncthreads();
        // A[m=d][k=s] = sK[s][d]; B[k=s][n=v] = sV[s][v]
        #pragma unroll
        for (int ks = 0; ks < KT/8; ks++){
            int sb = ks*8;
            uint32_t a0 = __float_as_uint(sK[sb+tig  ][m_base+gid  ]);
            uint32_t a1 = __float_as_uint(sK[sb+tig  ][m_base+gid+8]);
            uint32_t a2 = __float_as_uint(sK[sb+tig+4][m_base+gid  ]);
            uint32_t a3 = __float_as_uint(sK[sb+tig+4][m_base+gid+8]);
            #pragma unroll
            for (int nt = 0; nt < 9; nt++){
                uint32_t b0 = __float_as_uint(sV[sb+tig  ][nt*8+gid]);
                uint32_t b1 = __float_as_uint(sV[sb+tig+4][nt*8+gid]);
                mma_tf32(c[nt], a0, a1, a2, a3, b0, b1);
            }
        }
    }

    float* dst = g_kv + (size_t)head*DD*DD;
    int r0 = m_base + gid, r1 = r0 + 8;
    #pragma unroll
    for (int nt = 0; nt < 8; nt++){
        int col = nt*8 + 2*tig;
        atomicAdd(&dst[r0*DD + col    ], c[nt][0]);
        atomicAdd(&dst[r0*DD + col + 1], c[nt][1]);
        atomicAdd(&dst[r1*DD + col    ], c[nt][2]);
        atomicAdd(&dst[r1*DD + col + 1], c[nt][3]);
    }
    if (tig == 0){   // N-tile 8, col 64 = k1
        atomicAdd(&g_k1[head*DD + r0], c[8][0]);
        atomicAdd(&g_k1[head*DD + r1], c[8][2]);
    }
}

// Out = phiQ @ KV (per head), normalized. N-tile 8 col 64 = norm via k1 column.
// grid (NHEAD, SS/64), 128 threads = 4 warps; warp w owns s-rows [16w,16w+16) of the tile.
__global__ __launch_bounds__(128) void out_kernel(const float* __restrict__ Q,
                                                  float* __restrict__ O){
    int head = blockIdx.x;
    int tid  = threadIdx.x;
    int lane = tid & 31, warp = tid >> 5;
    int gid  = lane >> 2, tig = lane & 3;

    __shared__ float sQ[64][QSTRIDE];   // phi(q/8) tf32; [s][d]
    __shared__ float skv[64][KSTRIDE];  // KV tf32; [d][v]; col64=k1, 65..71=0

    int s0 = blockIdx.y * 64;
    const float* Qb = Q + ((size_t)head*SS + s0)*DD;

    for (int i = tid; i < 64*16; i += 128){
        int r = i >> 4, c4 = i & 15;
        float4 q = ((const float4*)(Qb + (size_t)r*DD))[c4];
        q.x = tf32r(phi_f(q.x*0.125f)); q.y = tf32r(phi_f(q.y*0.125f));
        q.z = tf32r(phi_f(q.z*0.125f)); q.w = tf32r(phi_f(q.w*0.125f));
        ((float4*)&sQ[r][0])[c4] = q;
    }
    const float4* kvsrc = (const float4*)(g_kv + (size_t)head*DD*DD);
    for (int i = tid; i < 64*16; i += 128){
        int r = i >> 4, c4 = i & 15;
        float4 v = kvsrc[i];
        v.x = tf32r(v.x); v.y = tf32r(v.y); v.z = tf32r(v.z); v.w = tf32r(v.w);
        ((float4*)&skv[r][0])[c4] = v;
    }
    for (int i = tid; i < 64*8; i += 128){
        int r = i >> 3, cc = 64 + (i & 7);
        skv[r][cc] = (cc == 64) ? tf32r(g_k1[head*DD + r]) : 0.0f;
    }
    __syncthreads();

    float c[9][4];
    #pragma unroll
    for (int nt=0; nt<9; nt++){ c[nt][0]=0.f; c[nt][1]=0.f; c[nt][2]=0.f; c[nt][3]=0.f; }

    int m_base = warp * 16;
    // A[m=s][k=d] = sQ[s][d]; B[k=d][n=v] = skv[d][v]
    #pragma unroll
    for (int kd = 0; kd < 8; kd++){
        int kb = kd*8;
        uint32_t a0 = __float_as_uint(sQ[m_base+gid  ][kb+tig  ]);
        uint32_t a1 = __float_as_uint(sQ[m_base+gid+8][kb+tig  ]);
        uint32_t a2 = __float_as_uint(sQ[m_base+gid  ][kb+tig+4]);
        uint32_t a3 = __float_as_uint(sQ[m_base+gid+8][kb+tig+4]);
        #pragma unroll
        for (int nt = 0; nt < 9; nt++){
            uint32_t b0 = __float_as_uint(skv[kb+tig  ][nt*8+gid]);
            uint32_t b1 = __float_as_uint(skv[kb+tig+4][nt*8+gid]);
            mma_tf32(c[nt], a0, a1, a2, a3, b0, b1);
        }
    }

    // norm for row (m_base+gid) sits in lane gid*4's c[8][0]; row+8 in c[8][2]
    float n0 = __shfl_sync(0xffffffffu, c[8][0], lane & 28);
    float n1 = __shfl_sync(0xffffffffu, c[8][2], lane & 28);
    float i0 = 1.0f / (n0 + EPSF);
    float i1 = 1.0f / (n1 + EPSF);

    float* Ob = O + ((size_t)head*SS + s0)*DD;
    int r0 = m_base + gid, r1 = r0 + 8;
    #pragma unroll
    for (int nt = 0; nt < 8; nt++){
        int col = nt*8 + 2*tig;
        float2 o0; o0.x = c[nt][0]*i0; o0.y = c[nt][1]*i0;
        float2 o1; o1.x = c[nt][2]*i1; o1.y = c[nt][3]*i1;
        *(float2*)(Ob + (size_t)r0*DD + col) = o0;
        *(float2*)(Ob + (size_t)r1*DD + col) = o1;
    }
}

extern "C" void kernel_launch(void* const* d_in, const int* in_sizes, int n_in,
                              void* d_out, int out_size){
    const float* Q    = (const float*)d_in[0];
    const float* K    = (const float*)d_in[1];
    const float* V    = (const float*)d_in[2];
    const float* mask = (const float*)d_in[3];
    float* O = (float*)d_out;

    zero_kernel<<<(NHEAD*DD*DD + 255)/256, 256>>>();
    kv_kernel<<<dim3(NHEAD, NCHUNK), 128>>>(K, V, mask);
    out_kernel<<<dim3(NHEAD, SS/64), 128>>>(Q, O);
}

// round 4
// speedup vs baseline: 2.0224x; 1.1503x over previous
#include <cuda_runtime.h>
#include <cuda_fp16.h>
#include <cstdint>

#define BB 4
#define HH 16
#define SS 4096
#define DD 64
#define NHEAD (BB*HH)
#define NCHUNK 8
#define CHUNK (SS/NCHUNK)   // 512
#define KT 64               // s-rows per smem tile in kv kernel
#define EPSF 1e-6f
#define STR 72              // padded half cols (144B row stride, conflict-free LDSM)

// scratch: per-head kv_term [64][64] and k_one [64]
__device__ float g_kv[NHEAD*DD*DD];
__device__ float g_k1[NHEAD*DD];

__device__ __forceinline__ float phi_f(float x){
    return x > 0.0f ? x + 1.0f : __expf(x);   // elu(x)+1
}
__device__ __forceinline__ uint32_t sptr(const void* p){
    return (uint32_t)__cvta_generic_to_shared(p);
}
__device__ __forceinline__ void ldsm4t(uint32_t d[4], uint32_t addr){
    asm volatile("ldmatrix.sync.aligned.m8n8.x4.trans.shared.b16 {%0,%1,%2,%3}, [%4];"
        : "=r"(d[0]),"=r"(d[1]),"=r"(d[2]),"=r"(d[3]) : "r"(addr));
}
__device__ __forceinline__ void ldsm4(uint32_t d[4], uint32_t addr){
    asm volatile("ldmatrix.sync.aligned.m8n8.x4.shared.b16 {%0,%1,%2,%3}, [%4];"
        : "=r"(d[0]),"=r"(d[1]),"=r"(d[2]),"=r"(d[3]) : "r"(addr));
}
__device__ __forceinline__ void ldsm2t(uint32_t d[2], uint32_t addr){
    asm volatile("ldmatrix.sync.aligned.m8n8.x2.trans.shared.b16 {%0,%1}, [%2];"
        : "=r"(d[0]),"=r"(d[1]) : "r"(addr));
}
__device__ __forceinline__ void mma_f16(float c[4], const uint32_t a[4], const uint32_t b[2]){
    asm volatile("mma.sync.aligned.m16n8k16.row.col.f32.f16.f16.f32 "
        "{%0,%1,%2,%3},{%4,%5,%6,%7},{%8,%9},{%0,%1,%2,%3};"
        : "+f"(c[0]),"+f"(c[1]),"+f"(c[2]),"+f"(c[3])
        : "r"(a[0]),"r"(a[1]),"r"(a[2]),"r"(a[3]),"r"(b[0]),"r"(b[1]));
}

__global__ void zero_kernel(){
    int i = blockIdx.x*blockDim.x + threadIdx.x;
    if (i < NHEAD*DD*DD) g_kv[i] = 0.0f;
    if (i < NHEAD*DD)    g_k1[i] = 0.0f;
}

// KV = phiK^T @ [V | 1]  via fp16 MMA. grid (NHEAD, NCHUNK), 128 thr = 4 warps.
// warp w owns d-rows [16w,16w+16); 9 N-tiles (tile 8 col 64 = k1 via ones column).
__global__ __launch_bounds__(128) void kv_kernel(const float* __restrict__ K,
                                                 const float* __restrict__ V,
                                                 const float* __restrict__ mask){
    int head = blockIdx.x;
    int b = head / HH;
    int tid  = threadIdx.x;
    int lane = tid & 31, warp = tid >> 5;

    __shared__ __align__(16) __half sK[KT][STR];   // [s][d], phi(K)*mask
    __shared__ __align__(16) __half sV[KT][STR];   // [s][v], col64=1, 65..71=0

    for (int i = tid; i < KT*8; i += 128){
        int r = i >> 3, cc = 64 + (i & 7);
        sV[r][cc] = (cc == 64) ? __float2half(1.0f) : __float2half(0.0f);
    }

    float c[9][4];
    #pragma unroll
    for (int nt=0; nt<9; nt++){ c[nt][0]=0.f; c[nt][1]=0.f; c[nt][2]=0.f; c[nt][3]=0.f; }

    const float* Kb = K + (size_t)head*SS*DD;
    const float* Vb = V + (size_t)head*SS*DD;
    const float* Mb = mask + (size_t)b*SS;
    int s0 = blockIdx.y * CHUNK;
    int m0 = warp * 16;

    // LDSM lane address pieces
    int li   = lane & 7;
    int aRow = li + ((lane >> 4) << 3);            // k offset within 16
    int aCol = m0 + (((lane >> 3) & 1) << 3);      // m0 or m0+8
    int bRow = li + (((lane >> 3) & 1) << 3);      // k offset within 16
    uint32_t aBase = sptr(&sK[aRow][aCol]);
    uint32_t bBase = sptr(&sV[bRow][0]);

    for (int t = 0; t < CHUNK; t += KT){
        __syncthreads();
        // load KT rows of K (phi+mask) and V: 64 rows x 16 float4, 8 each per thread
        #pragma unroll
        for (int i = tid; i < KT*16; i += 128){
            int r = i >> 4, c4 = i & 15;
            int row = s0 + t + r;
            float4 kk = ((const float4*)(Kb + (size_t)row*DD))[c4];
            float m = Mb[row];
            __half2 k0 = __floats2half2_rn(phi_f(kk.x)*m, phi_f(kk.y)*m);
            __half2 k1 = __floats2half2_rn(phi_f(kk.z)*m, phi_f(kk.w)*m);
            ((__half2*)&sK[r][0])[c4*2  ] = k0;
            ((__half2*)&sK[r][0])[c4*2+1] = k1;
            float4 vv = ((const float4*)(Vb + (size_t)row*DD))[c4];
            ((__half2*)&sV[r][0])[c4*2  ] = __floats2half2_rn(vv.x, vv.y);
            ((__half2*)&sV[r][0])[c4*2+1] = __floats2half2_rn(vv.z, vv.w);
        }
        __syncthreads();
        #pragma unroll
        for (int ks = 0; ks < KT/16; ks++){
            uint32_t a[4];
            ldsm4t(a, aBase + ks*16*(STR*2));
            #pragma unroll
            for (int nt = 0; nt < 9; nt++){
                uint32_t bb[2];
                ldsm2t(bb, bBase + ks*16*(STR*2) + nt*16);
                mma_f16(c[nt], a, bb);
            }
        }
    }

    int gid = lane >> 2, tig = lane & 3;
    float* dst = g_kv + (size_t)head*DD*DD;
    int r0 = m0 + gid, r1 = r0 + 8;
    #pragma unroll
    for (int nt = 0; nt < 8; nt++){
        int col = nt*8 + 2*tig;
        atomicAdd(&dst[r0*DD + col    ], c[nt][0]);
        atomicAdd(&dst[r0*DD + col + 1], c[nt][1]);
        atomicAdd(&dst[r1*DD + col    ], c[nt][2]);
        atomicAdd(&dst[r1*DD + col + 1], c[nt][3]);
    }
    if (tig == 0){
        atomicAdd(&g_k1[head*DD + r0], c[8][0]);
        atomicAdd(&g_k1[head*DD + r1], c[8][2]);
    }
}

// Out = phiQ @ [KV | k1], normalized. grid (NHEAD, SS/128), 256 thr = 8 warps.
// warp w owns s-rows [16w,16w+16) of the 128-row tile.
__global__ __launch_bounds__(256) void out_kernel(const float* __restrict__ Q,
                                                  float* __restrict__ O){
    int head = blockIdx.x;
    int tid  = threadIdx.x;
    int lane = tid & 31, warp = tid >> 5;

    __shared__ __align__(16) __half sQ[128][STR];  // [s][d], phi(q/8)
    __shared__ __align__(16) __half skv[DD][STR];  // [d][v], col64=k1, 65..71=0

    int s0 = blockIdx.y * 128;
    const float* Qb = Q + ((size_t)head*SS + s0)*DD;

    #pragma unroll
    for (int i = tid; i < 128*16; i += 256){
        int r = i >> 4, c4 = i & 15;
        float4 q = ((const float4*)(Qb + (size_t)r*DD))[c4];
        ((__half2*)&sQ[r][0])[c4*2  ] = __floats2half2_rn(phi_f(q.x*0.125f), phi_f(q.y*0.125f));
        ((__half2*)&sQ[r][0])[c4*2+1] = __floats2half2_rn(phi_f(q.z*0.125f), phi_f(q.w*0.125f));
    }
    const float4* kvsrc = (const float4*)(g_kv + (size_t)head*DD*DD);
    #pragma unroll
    for (int i = tid; i < DD*16; i += 256){
        int r = i >> 4, c4 = i & 15;
        float4 v = kvsrc[i];
        ((__half2*)&skv[r][0])[c4*2  ] = __floats2half2_rn(v.x, v.y);
        ((__half2*)&skv[r][0])[c4*2+1] = __floats2half2_rn(v.z, v.w);
    }
    for (int i = tid; i < DD*8; i += 256){
        int r = i >> 3, cc = 64 + (i & 7);
        skv[r][cc] = (cc == 64) ? __float2half(g_k1[head*DD + r]) : __float2half(0.0f);
    }
    __syncthreads();

    float c[9][4];
    #pragma unroll
    for (int nt=0; nt<9; nt++){ c[nt][0]=0.f; c[nt][1]=0.f; c[nt][2]=0.f; c[nt][3]=0.f; }

    int m0 = warp * 16;
    int li = lane & 7;
    // A (row-major [m][k]) no-trans: lanes 0-7:(m0+i,k0) 8-15:(m0+8+i,k0) 16-23:(m0+i,k0+8) 24-31:(m0+8+i,k0+8)
    int aRow = m0 + li + (((lane >> 3) & 1) << 3);
    int aCol = (lane >> 4) << 3;
    int bRow = li + (((lane >> 3) & 1) << 3);
    uint32_t aBase = sptr(&sQ[aRow][aCol]);
    uint32_t bBase = sptr(&skv[bRow][0]);

    #pragma unroll
    for (int ks = 0; ks < 4; ks++){
        uint32_t a[4];
        ldsm4(a, aBase + ks*16*2);        // advance k by 16 halves = 32B within row
        #pragma unroll
        for (int nt = 0; nt < 9; nt++){
            uint32_t bb[2];
            ldsm2t(bb, bBase + ks*16*(STR*2) + nt*16);
            mma_f16(c[nt], a, bb);
        }
    }

    int gid = lane >> 2, tig = lane & 3;
    float n0 = __shfl_sync(0xffffffffu, c[8][0], lane & 28);
    float n1 = __shfl_sync(0xffffffffu, c[8][2], lane & 28);
    float i0 = 1.0f / (n0 + EPSF);
    float i1 = 1.0f / (n1 + EPSF);

    float* Ob = O + ((size_t)head*SS + s0)*DD;
    int r0 = m0 + gid, r1 = r0 + 8;
    #pragma unroll
    for (int nt = 0; nt < 8; nt++){
        int col = nt*8 + 2*tig;
        float2 o0; o0.x = c[nt][0]*i0; o0.y = c[nt][1]*i0;
        float2 o1; o1.x = c[nt][2]*i1; o1.y = c[nt][3]*i1;
        *(float2*)(Ob + (size_t)r0*DD + col) = o0;
        *(float2*)(Ob + (size_t)r1*DD + col) = o1;
    }
}

extern "C" void kernel_launch(void* const* d_in, const int* in_sizes, int n_in,
                              void* d_out, int out_size){
    const float* Q    = (const float*)d_in[0];
    const float* K    = (const float*)d_in[1];
    const float* V    = (const float*)d_in[2];
    const float* mask = (const float*)d_in[3];
    float* O = (float*)d_out;

    zero_kernel<<<(NHEAD*DD*DD + 255)/256, 256>>>();
    kv_kernel<<<dim3(NHEAD, NCHUNK), 128>>>(K, V, mask);
    out_kernel<<<dim3(NHEAD, SS/128), 256>>>(Q, O);
}